// round 7
// baseline (speedup 1.0000x reference)
#include <cuda_runtime.h>
#include <cstdint>

// ---------------------------------------------------------------------------
// WindowAttention (Swin-style), GB300 sm_103a — fused, k-paired smem layouts.
// R7: weight (B) fragments loaded directly from L2-resident global tf32
//     arrays (no smem staging, no cp.async, no double-buffer barriers).
//     Full-block barriers cut to 3 (+1 named per-head).
// ---------------------------------------------------------------------------

__device__ uint32_t g_wqkvT[384 * 128];   // [n][k-paired]
__device__ uint32_t g_woutT[128 * 128];   // [n][k-paired]

__device__ __forceinline__ uint32_t f2tf(float f) {
    uint32_t r;
    asm("cvt.rna.tf32.f32 %0, %1;" : "=r"(r) : "f"(f));
    return r;
}

__device__ __forceinline__ void mma8(float* c, const uint32_t* a, const uint32_t* b) {
    asm volatile(
        "mma.sync.aligned.m16n8k8.row.col.f32.tf32.tf32.f32 "
        "{%0,%1,%2,%3}, {%4,%5,%6,%7}, {%8,%9}, {%0,%1,%2,%3};\n"
        : "+f"(c[0]), "+f"(c[1]), "+f"(c[2]), "+f"(c[3])
        : "r"(a[0]), "r"(a[1]), "r"(a[2]), "r"(a[3]), "r"(b[0]), "r"(b[1]));
}
// slot within an 8-wide k-group: [k0 k4 k1 k5 k2 k6 k3 k7]
__device__ __forceinline__ int SL(int c) { return ((c & 3) << 1) | (c >> 2); }

// ===========================================================================
// cvt: transpose + pair + tf32-convert weights
// ===========================================================================
__global__ void cvt_kernel(const float* __restrict__ wqkv,
                           const float* __restrict__ wout) {
    int i = blockIdx.x * 256 + threadIdx.x;
    if (i < 384 * 128) {
        int n = i >> 7, kp = i & 127;
        int g = kp >> 3, s = kp & 7;
        int k = g * 8 + (s >> 1) + ((s & 1) << 2);
        g_wqkvT[i] = f2tf(wqkv[k * 384 + n]);
    }
    if (i < 128 * 128) {
        int n = i >> 7, kp = i & 127;
        int g = kp >> 3, s = kp & 7;
        int k = g * 8 + (s >> 1) + ((s & 1) << 2);
        g_woutT[i] = f2tf(wout[k * 128 + n]);
    }
}

// ===========================================================================
// smem map (u32):
//  sQ 0..8704   sK 8704..17408   sV 17408..26112   (stride 136, paired)
//  sA 26112..34816 (phase 1 A; later sO)
//  sP 34816..53248 (4 heads x [64][72])
//  PE 53248  BO 53504   total 53632 u32 = 214528 B
// ===========================================================================
#define SQ_OFF 0
#define SK_OFF 8704
#define SV_OFF 17408
#define SA_OFF 26112
#define SP_OFF 34816
#define PE_OFF 53248
#define BO_OFF 53504
#define FU_SMEM (53632 * 4)

__global__ __launch_bounds__(512, 1)
void fused_kernel(const float* __restrict__ x,
                  const float* __restrict__ bout,
                  const float* __restrict__ pe,  const float* __restrict__ ul,
                  const float* __restrict__ lr,  float* __restrict__ out) {
    extern __shared__ uint32_t sm[];
    uint32_t* sQ = sm + SQ_OFF;
    uint32_t* sK = sm + SK_OFF;
    uint32_t* sV = sm + SV_OFF;
    uint32_t* sA = sm + SA_OFF;
    uint32_t* sP = sm + SP_OFF;
    uint32_t* sO = sm + SA_OFF;     // overlays sA (dead after phase 1)
    float* sPE = (float*)(sm + PE_OFF);
    float* sBO = (float*)(sm + BO_OFF);

    const int t = threadIdx.x;
    const int warp = t >> 5, lane = t & 31;
    const int gid = lane >> 2, tid4 = lane & 3;
    const int blk = blockIdx.x;
    const int bb = blk >> 8, win = blk & 255;
    const int wy = win >> 4, wx = win & 15;

    // ---- Phase 1 setup: warp tile 32 x 48 (grid 2 M x 8 N) ----
    const int gwm = warp & 1, gwn = warp >> 1;
    const int rowb1 = gwm * 32, colb1 = gwn * 48;

    // B fragment loader: step = kt*2+kk in 0..15, 6 n-tiles, direct from L2
    uint2 bA[12], bB[12];
    auto ldBkt = [&](uint2* dst, int kt) {
        #pragma unroll
        for (int kk = 0; kk < 2; kk++) {
            int kp = kt * 16 + kk * 8 + 2 * tid4;
            #pragma unroll
            for (int nt = 0; nt < 6; nt++)
                dst[kk * 6 + nt] =
                    *(const uint2*)&g_wqkvT[(size_t)(colb1 + nt * 8 + gid) * 128 + kp];
        }
    };
    ldBkt(bA, 0);
    ldBkt(bB, 1);

    // ---- A gather: rolled x rows, tf32, pair-interleaved ----
    {
        const int row_a = t >> 3, part = t & 7;
        const int ty = row_a >> 3, tx = row_a & 7;
        const int sh = (wy * 8 + ty + 4) & 127, sw = (wx * 8 + tx + 4) & 127;
        const float* aptr = x + (((size_t)bb * 128 + sh) * 128 + sw) * 128 + part * 16;
        uint32_t* ap = sA + row_a * 136;
        #pragma unroll
        for (int j4 = 0; j4 < 4; j4++) {
            float4 v = *(const float4*)(aptr + j4 * 4);
            int grp = part * 2 + (j4 >> 1);
            int odd = (j4 & 1);
            ap[grp * 8 + 0 + odd] = f2tf(v.x);
            ap[grp * 8 + 2 + odd] = f2tf(v.y);
            ap[grp * 8 + 4 + odd] = f2tf(v.z);
            ap[grp * 8 + 6 + odd] = f2tf(v.w);
        }
    }
    if (t < 225) sPE[t] = pe[t];
    if (t < 128) sBO[t] = bout[t];
    __syncthreads();                         // [FULL SYNC 1] sA/sPE/sBO ready

    // ---- Phase 1: QKV GEMM, barrier-free mainloop ----
    float acc[2][6][4];
    #pragma unroll
    for (int a = 0; a < 2; a++)
        #pragma unroll
        for (int b2 = 0; b2 < 6; b2++)
            #pragma unroll
            for (int c = 0; c < 4; c++) acc[a][b2][c] = 0.f;

    auto doKt = [&](int kt, const uint2* bf) {
        #pragma unroll
        for (int kk = 0; kk < 2; kk++) {
            int ka = kt * 16 + kk * 8 + 2 * tid4;
            uint2 a0m0 = *(const uint2*)&sA[(rowb1 + gid) * 136 + ka];
            uint2 a1m0 = *(const uint2*)&sA[(rowb1 + 8 + gid) * 136 + ka];
            uint2 a0m1 = *(const uint2*)&sA[(rowb1 + 16 + gid) * 136 + ka];
            uint2 a1m1 = *(const uint2*)&sA[(rowb1 + 24 + gid) * 136 + ka];
            uint32_t am0[4] = {a0m0.x, a1m0.x, a0m0.y, a1m0.y};
            uint32_t am1[4] = {a0m1.x, a1m1.x, a0m1.y, a1m1.y};
            #pragma unroll
            for (int nt = 0; nt < 6; nt++) {
                mma8(acc[0][nt], am0, (const uint32_t*)&bf[kk * 6 + nt]);
                mma8(acc[1][nt], am1, (const uint32_t*)&bf[kk * 6 + nt]);
            }
        }
    };
    #pragma unroll
    for (int kt = 0; kt < 8; kt += 2) {
        doKt(kt, bA);
        if (kt + 2 < 8) ldBkt(bA, kt + 2);
        doKt(kt + 1, bB);
        if (kt + 3 < 8) ldBkt(bB, kt + 3);
    }

    // epilogue: write Q/K/V (tf32, paired) into sQ/sK/sV
    {
        const int s0 = SL(2 * tid4), s1 = SL(2 * tid4 + 1);
        #pragma unroll
        for (int mt = 0; mt < 2; mt++) {
            int r0 = rowb1 + mt * 16 + gid, r1 = r0 + 8;
            #pragma unroll
            for (int nt = 0; nt < 6; nt++) {
                int gcol = colb1 + nt * 8;
                int seg = gcol >> 7, loc = gcol & 127;
                uint32_t* dst = sm + (seg == 0 ? SQ_OFF : seg == 1 ? SK_OFF : SV_OFF) + loc;
                dst[r0 * 136 + s0] = f2tf(acc[mt][nt][0]);
                dst[r0 * 136 + s1] = f2tf(acc[mt][nt][1]);
                dst[r1 * 136 + s0] = f2tf(acc[mt][nt][2]);
                dst[r1 * 136 + s1] = f2tf(acc[mt][nt][3]);
            }
        }
    }
    __syncthreads();                         // [FULL SYNC 2] Q/K/V visible

    // ---- Phase B: S = Q K^T (4 warps/head, 16 q-rows each) ----
    const int head = warp >> 2;
    const int wrb = (warp & 3) * 16;
    const int hoff = head * 32;
    float sacc[8][4];
    #pragma unroll
    for (int b2 = 0; b2 < 8; b2++)
        #pragma unroll
        for (int c = 0; c < 4; c++) sacc[b2][c] = 0.f;

    #pragma unroll
    for (int kk = 0; kk < 32; kk += 8) {
        uint2 a0 = *(const uint2*)&sQ[(wrb + gid) * 136 + hoff + kk + 2 * tid4];
        uint2 a1 = *(const uint2*)&sQ[(wrb + 8 + gid) * 136 + hoff + kk + 2 * tid4];
        uint32_t a[4] = {a0.x, a1.x, a0.y, a1.y};
        #pragma unroll
        for (int nt = 0; nt < 8; nt++) {
            int key = nt * 8 + gid;
            uint2 b = *(const uint2*)&sK[key * 136 + hoff + kk + 2 * tid4];
            mma8(sacc[nt], a, (const uint32_t*)&b);
        }
    }

    // ---- Phase C: bias + masks + softmax ----
    const float scale = 0.17677669529663689f;
    const bool addUL = (wy == 15);
    const bool addLR = (wx == 15);

    #pragma unroll
    for (int rh = 0; rh < 2; rh++) {
        const int i = wrb + rh * 8 + gid;
        const int iy = i >> 3, ix = i & 7;
        float vrow[16];
        float m = -1e30f;
        #pragma unroll
        for (int nt = 0; nt < 8; nt++) {
            #pragma unroll
            for (int u = 0; u < 2; u++) {
                int j = nt * 8 + tid4 * 2 + u;
                int jy = j >> 3, jx = j & 7;
                float v = sacc[nt][rh * 2 + u] * scale
                        + sPE[(jy - iy + 7) * 15 + (jx - ix + 7)];
                if (addUL) v += ul[i * 64 + j];
                if (addLR) v += lr[i * 64 + j];
                vrow[nt * 2 + u] = v;
                m = fmaxf(m, v);
            }
        }
        m = fmaxf(m, __shfl_xor_sync(0xffffffffu, m, 1));
        m = fmaxf(m, __shfl_xor_sync(0xffffffffu, m, 2));
        float sum = 0.f;
        #pragma unroll
        for (int u2 = 0; u2 < 16; u2++) {
            vrow[u2] = __expf(vrow[u2] - m);
            sum += vrow[u2];
        }
        sum += __shfl_xor_sync(0xffffffffu, sum, 1);
        sum += __shfl_xor_sync(0xffffffffu, sum, 2);
        float inv = 1.f / sum;
        #pragma unroll
        for (int nt = 0; nt < 8; nt++) {
            #pragma unroll
            for (int u = 0; u < 2; u++)
                sacc[nt][rh * 2 + u] = vrow[nt * 2 + u] * inv;
        }
    }

    // ---- Phase D: store P (tf32, paired) into sP[head] ----
    uint32_t* myP = sP + head * (64 * 72);
    {
        const int s0 = SL(2 * tid4), s1 = SL(2 * tid4 + 1);
        #pragma unroll
        for (int rh = 0; rh < 2; rh++) {
            int i = wrb + rh * 8 + gid;
            #pragma unroll
            for (int nt = 0; nt < 8; nt++) {
                myP[i * 72 + nt * 8 + s0] = f2tf(sacc[nt][rh * 2]);
                myP[i * 72 + nt * 8 + s1] = f2tf(sacc[nt][rh * 2 + 1]);
            }
        }
    }
    // named barrier: only the 4 warps of this head need sP[head] coherent
    asm volatile("bar.sync %0, %1;" :: "r"(1 + head), "r"(128) : "memory");

    // ---- Phase E: O = P @ V ----
    float oacc[4][4];
    #pragma unroll
    for (int b2 = 0; b2 < 4; b2++)
        #pragma unroll
        for (int c = 0; c < 4; c++) oacc[b2][c] = 0.f;
    const int dslot = SL(gid);

    #pragma unroll
    for (int kk = 0; kk < 8; kk++) {
        uint2 a0 = *(const uint2*)&myP[(wrb + gid) * 72 + kk * 8 + 2 * tid4];
        uint2 a1 = *(const uint2*)&myP[(wrb + 8 + gid) * 72 + kk * 8 + 2 * tid4];
        uint32_t a[4] = {a0.x, a1.x, a0.y, a1.y};
        #pragma unroll
        for (int nt = 0; nt < 4; nt++) {
            int dcol = hoff + nt * 8 + dslot;
            uint32_t b[2];
            b[0] = sV[(kk * 8 + tid4) * 136 + dcol];
            b[1] = sV[(kk * 8 + tid4 + 4) * 136 + dcol];
            mma8(oacc[nt], a, b);
        }
    }

    // ---- Phase F: store O (tf32, paired) into sO (overlays sA — dead) ----
    {
        const int s0 = SL(2 * tid4), s1 = SL(2 * tid4 + 1);
        #pragma unroll
        for (int nt = 0; nt < 4; nt++) {
            int grp = hoff + nt * 8;
            sO[(wrb + gid) * 136 + grp + s0]     = f2tf(oacc[nt][0]);
            sO[(wrb + gid) * 136 + grp + s1]     = f2tf(oacc[nt][1]);
            sO[(wrb + 8 + gid) * 136 + grp + s0] = f2tf(oacc[nt][2]);
            sO[(wrb + 8 + gid) * 136 + grp + s1] = f2tf(oacc[nt][3]);
        }
    }
    __syncthreads();                         // [FULL SYNC 3] sO visible

    // ---- Phase G: Y = O @ w_out + b_out (w_out frags direct from L2) ----
    const int pwm = warp & 3, pwn = warp >> 2;   // 4x4 grid, tile 16x32
    float yacc[4][4];
    #pragma unroll
    for (int b2 = 0; b2 < 4; b2++)
        #pragma unroll
        for (int c = 0; c < 4; c++) yacc[b2][c] = 0.f;

    uint2 wA[4], wB[4];
    auto ldW = [&](uint2* dst, int kk) {
        int kp = kk * 8 + 2 * tid4;
        #pragma unroll
        for (int nt = 0; nt < 4; nt++)
            dst[nt] = *(const uint2*)&g_woutT[(size_t)(pwn * 32 + nt * 8 + gid) * 128 + kp];
    };
    ldW(wA, 0);
    ldW(wB, 1);

    auto doKk = [&](int kk, const uint2* wf) {
        uint2 a0 = *(const uint2*)&sO[(pwm * 16 + gid) * 136 + kk * 8 + 2 * tid4];
        uint2 a1 = *(const uint2*)&sO[(pwm * 16 + 8 + gid) * 136 + kk * 8 + 2 * tid4];
        uint32_t a[4] = {a0.x, a1.x, a0.y, a1.y};
        #pragma unroll
        for (int nt = 0; nt < 4; nt++)
            mma8(yacc[nt], a, (const uint32_t*)&wf[nt]);
    };
    #pragma unroll
    for (int kk = 0; kk < 16; kk += 2) {
        doKk(kk, wA);
        if (kk + 2 < 16) ldW(wA, kk + 2);
        doKk(kk + 1, wB);
        if (kk + 3 < 16) ldW(wB, kk + 3);
    }

    #pragma unroll
    for (int rh = 0; rh < 2; rh++) {
        int i = pwm * 16 + rh * 8 + gid;
        int ty = i >> 3, tx = i & 7;
        int h = (wy * 8 + ty + 4) & 127;
        int w = (wx * 8 + tx + 4) & 127;
        float* orow = out + (((size_t)bb * 128 + h) * 128 + w) * 128;
        #pragma unroll
        for (int nt = 0; nt < 4; nt++) {
            int c = pwn * 32 + nt * 8 + tid4 * 2;
            float2 v = make_float2(yacc[nt][rh * 2]     + sBO[c],
                                   yacc[nt][rh * 2 + 1] + sBO[c + 1]);
            *(float2*)(orow + c) = v;
        }
    }
}

// ===========================================================================
extern "C" void kernel_launch(void* const* d_in, const int* in_sizes, int n_in,
                              void* d_out, int out_size) {
    const float* x    = (const float*)d_in[0];
    const float* wqkv = (const float*)d_in[1];
    const float* wout = (const float*)d_in[2];
    const float* bout = (const float*)d_in[3];
    const float* pe   = (const float*)d_in[4];
    const float* ul   = (const float*)d_in[5];
    const float* lr   = (const float*)d_in[6];
    float* out = (float*)d_out;

    cudaFuncSetAttribute(fused_kernel, cudaFuncAttributeMaxDynamicSharedMemorySize, FU_SMEM);

    cvt_kernel<<<192, 256>>>(wqkv, wout);
    fused_kernel<<<4096, 512, FU_SMEM>>>(x, bout, pe, ul, lr, out);
}

// round 8
// speedup vs baseline: 1.4631x; 1.4631x over previous
#include <cuda_runtime.h>
#include <cstdint>

// ---------------------------------------------------------------------------
// WindowAttention (Swin-style), GB300 sm_103a — fused, k-paired smem layouts.
// R8: weights stored FRAGMENT-LINEAR in global (one coalesced 256B LDG.64 per
//     mma B-fragment, L1/L2-resident). No cp.async staging, 3 full barriers.
// ---------------------------------------------------------------------------

__device__ uint32_t g_wqkvF[48 * 16 * 64];   // [n8][step][lane*2] fragment-linear
__device__ uint32_t g_woutF[16 * 16 * 64];

__device__ __forceinline__ uint32_t f2tf(float f) {
    uint32_t r;
    asm("cvt.rna.tf32.f32 %0, %1;" : "=r"(r) : "f"(f));
    return r;
}

__device__ __forceinline__ void mma8(float* c, const uint32_t* a, const uint32_t* b) {
    asm volatile(
        "mma.sync.aligned.m16n8k8.row.col.f32.tf32.tf32.f32 "
        "{%0,%1,%2,%3}, {%4,%5,%6,%7}, {%8,%9}, {%0,%1,%2,%3};\n"
        : "+f"(c[0]), "+f"(c[1]), "+f"(c[2]), "+f"(c[3])
        : "r"(a[0]), "r"(a[1]), "r"(a[2]), "r"(a[3]), "r"(b[0]), "r"(b[1]));
}
// slot within an 8-wide k-group: [k0 k4 k1 k5 k2 k6 k3 k7]
__device__ __forceinline__ int SL(int c) { return ((c & 3) << 1) | (c >> 2); }

// ===========================================================================
// cvt: weights -> tf32 fragment-linear layout.
// fragment element (n8, step, lane, j):  n = n8*8 + (lane>>2),
//                                        k = step*8 + (lane&3) + 4*j
// ===========================================================================
__global__ void cvt_kernel(const float* __restrict__ wqkv,
                           const float* __restrict__ wout) {
    int i = blockIdx.x * 256 + threadIdx.x;   // 0..49151
    {
        int n8 = i >> 10, rem = i & 1023;
        int step = rem >> 6, rem2 = rem & 63;
        int lane = rem2 >> 1, j = rem2 & 1;
        int n = n8 * 8 + (lane >> 2);
        int k = step * 8 + (lane & 3) + 4 * j;
        g_wqkvF[i] = f2tf(wqkv[k * 384 + n]);
    }
    if (i < 16 * 16 * 64) {
        int n8 = i >> 10, rem = i & 1023;
        int step = rem >> 6, rem2 = rem & 63;
        int lane = rem2 >> 1, j = rem2 & 1;
        int n = n8 * 8 + (lane >> 2);
        int k = step * 8 + (lane & 3) + 4 * j;
        g_woutF[i] = f2tf(wout[k * 128 + n]);
    }
}

// ===========================================================================
// smem map (u32):
//  sQ 0..8704   sK 8704..17408   sV 17408..26112   (stride 136, paired)
//  sA 26112..34816 (phase 1 A; later sO)
//  sP 34816..53248 (4 heads x [64][72])
//  PE 53248  BO 53504   total 53632 u32 = 214528 B
// ===========================================================================
#define SQ_OFF 0
#define SK_OFF 8704
#define SV_OFF 17408
#define SA_OFF 26112
#define SP_OFF 34816
#define PE_OFF 53248
#define BO_OFF 53504
#define FU_SMEM (53632 * 4)

__global__ __launch_bounds__(512, 1)
void fused_kernel(const float* __restrict__ x,
                  const float* __restrict__ bout,
                  const float* __restrict__ pe,  const float* __restrict__ ul,
                  const float* __restrict__ lr,  float* __restrict__ out) {
    extern __shared__ uint32_t sm[];
    uint32_t* sQ = sm + SQ_OFF;
    uint32_t* sK = sm + SK_OFF;
    uint32_t* sV = sm + SV_OFF;
    uint32_t* sA = sm + SA_OFF;
    uint32_t* sP = sm + SP_OFF;
    uint32_t* sO = sm + SA_OFF;     // overlays sA (dead after phase 1)
    float* sPE = (float*)(sm + PE_OFF);
    float* sBO = (float*)(sm + BO_OFF);

    const int t = threadIdx.x;
    const int warp = t >> 5, lane = t & 31;
    const int gid = lane >> 2, tid4 = lane & 3;
    const int blk = blockIdx.x;
    const int bb = blk >> 8, win = blk & 255;
    const int wy = win >> 4, wx = win & 15;

    // ---- Phase 1 setup: warp tile 32 x 48 (grid 2 M x 8 N) ----
    const int gwm = warp & 1, gwn = warp >> 1;
    const int rowb1 = gwm * 32;

    // B fragment loader: fragment-linear, one coalesced LDG.64 per fragment
    uint2 bA[12], bB[12];
    auto ldBkt = [&](uint2* dst, int kt) {
        #pragma unroll
        for (int kk = 0; kk < 2; kk++) {
            int step = kt * 2 + kk;
            #pragma unroll
            for (int nt = 0; nt < 6; nt++) {
                int n8g = gwn * 6 + nt;
                dst[kk * 6 + nt] =
                    *(const uint2*)&g_wqkvF[(n8g * 16 + step) * 64 + lane * 2];
            }
        }
    };
    ldBkt(bA, 0);
    ldBkt(bB, 1);

    // ---- A gather: rolled x rows, tf32, pair-interleaved ----
    {
        const int row_a = t >> 3, part = t & 7;
        const int ty = row_a >> 3, tx = row_a & 7;
        const int sh = (wy * 8 + ty + 4) & 127, sw = (wx * 8 + tx + 4) & 127;
        const float* aptr = x + (((size_t)bb * 128 + sh) * 128 + sw) * 128 + part * 16;
        uint32_t* ap = sA + row_a * 136;
        #pragma unroll
        for (int j4 = 0; j4 < 4; j4++) {
            float4 v = *(const float4*)(aptr + j4 * 4);
            int grp = part * 2 + (j4 >> 1);
            int odd = (j4 & 1);
            ap[grp * 8 + 0 + odd] = f2tf(v.x);
            ap[grp * 8 + 2 + odd] = f2tf(v.y);
            ap[grp * 8 + 4 + odd] = f2tf(v.z);
            ap[grp * 8 + 6 + odd] = f2tf(v.w);
        }
    }
    if (t < 225) sPE[t] = pe[t];
    if (t < 128) sBO[t] = bout[t];
    __syncthreads();                         // [FULL SYNC 1] sA/sPE/sBO ready

    // ---- Phase 1: QKV GEMM, barrier-free mainloop ----
    float acc[2][6][4];
    #pragma unroll
    for (int a = 0; a < 2; a++)
        #pragma unroll
        for (int b2 = 0; b2 < 6; b2++)
            #pragma unroll
            for (int c = 0; c < 4; c++) acc[a][b2][c] = 0.f;

    auto doKt = [&](int kt, const uint2* bf) {
        #pragma unroll
        for (int kk = 0; kk < 2; kk++) {
            int ka = kt * 16 + kk * 8 + 2 * tid4;
            uint2 a0m0 = *(const uint2*)&sA[(rowb1 + gid) * 136 + ka];
            uint2 a1m0 = *(const uint2*)&sA[(rowb1 + 8 + gid) * 136 + ka];
            uint2 a0m1 = *(const uint2*)&sA[(rowb1 + 16 + gid) * 136 + ka];
            uint2 a1m1 = *(const uint2*)&sA[(rowb1 + 24 + gid) * 136 + ka];
            uint32_t am0[4] = {a0m0.x, a1m0.x, a0m0.y, a1m0.y};
            uint32_t am1[4] = {a0m1.x, a1m1.x, a0m1.y, a1m1.y};
            #pragma unroll
            for (int nt = 0; nt < 6; nt++) {
                mma8(acc[0][nt], am0, (const uint32_t*)&bf[kk * 6 + nt]);
                mma8(acc[1][nt], am1, (const uint32_t*)&bf[kk * 6 + nt]);
            }
        }
    };
    #pragma unroll
    for (int kt = 0; kt < 8; kt += 2) {
        doKt(kt, bA);
        if (kt + 2 < 8) ldBkt(bA, kt + 2);
        doKt(kt + 1, bB);
        if (kt + 3 < 8) ldBkt(bB, kt + 3);
    }

    // epilogue: write Q/K/V (tf32, paired) into sQ/sK/sV
    {
        const int s0 = SL(2 * tid4), s1 = SL(2 * tid4 + 1);
        #pragma unroll
        for (int mt = 0; mt < 2; mt++) {
            int r0 = rowb1 + mt * 16 + gid, r1 = r0 + 8;
            #pragma unroll
            for (int nt = 0; nt < 6; nt++) {
                int gcol = gwn * 48 + nt * 8;
                int seg = gcol >> 7, loc = gcol & 127;
                uint32_t* dst = sm + (seg == 0 ? SQ_OFF : seg == 1 ? SK_OFF : SV_OFF) + loc;
                dst[r0 * 136 + s0] = f2tf(acc[mt][nt][0]);
                dst[r0 * 136 + s1] = f2tf(acc[mt][nt][1]);
                dst[r1 * 136 + s0] = f2tf(acc[mt][nt][2]);
                dst[r1 * 136 + s1] = f2tf(acc[mt][nt][3]);
            }
        }
    }
    __syncthreads();                         // [FULL SYNC 2] Q/K/V visible

    // ---- Phase B: S = Q K^T (4 warps/head, 16 q-rows each) ----
    const int head = warp >> 2;
    const int wrb = (warp & 3) * 16;
    const int hoff = head * 32;
    float sacc[8][4];
    #pragma unroll
    for (int b2 = 0; b2 < 8; b2++)
        #pragma unroll
        for (int c = 0; c < 4; c++) sacc[b2][c] = 0.f;

    #pragma unroll
    for (int kk = 0; kk < 32; kk += 8) {
        uint2 a0 = *(const uint2*)&sQ[(wrb + gid) * 136 + hoff + kk + 2 * tid4];
        uint2 a1 = *(const uint2*)&sQ[(wrb + 8 + gid) * 136 + hoff + kk + 2 * tid4];
        uint32_t a[4] = {a0.x, a1.x, a0.y, a1.y};
        #pragma unroll
        for (int nt = 0; nt < 8; nt++) {
            int key = nt * 8 + gid;
            uint2 b = *(const uint2*)&sK[key * 136 + hoff + kk + 2 * tid4];
            mma8(sacc[nt], a, (const uint32_t*)&b);
        }
    }

    // ---- Phase C: bias + masks + softmax ----
    const float scale = 0.17677669529663689f;
    const bool addUL = (wy == 15);
    const bool addLR = (wx == 15);

    #pragma unroll
    for (int rh = 0; rh < 2; rh++) {
        const int i = wrb + rh * 8 + gid;
        const int iy = i >> 3, ix = i & 7;
        float vrow[16];
        float m = -1e30f;
        #pragma unroll
        for (int nt = 0; nt < 8; nt++) {
            #pragma unroll
            for (int u = 0; u < 2; u++) {
                int j = nt * 8 + tid4 * 2 + u;
                int jy = j >> 3, jx = j & 7;
                float v = sacc[nt][rh * 2 + u] * scale
                        + sPE[(jy - iy + 7) * 15 + (jx - ix + 7)];
                if (addUL) v += ul[i * 64 + j];
                if (addLR) v += lr[i * 64 + j];
                vrow[nt * 2 + u] = v;
                m = fmaxf(m, v);
            }
        }
        m = fmaxf(m, __shfl_xor_sync(0xffffffffu, m, 1));
        m = fmaxf(m, __shfl_xor_sync(0xffffffffu, m, 2));
        float sum = 0.f;
        #pragma unroll
        for (int u2 = 0; u2 < 16; u2++) {
            vrow[u2] = __expf(vrow[u2] - m);
            sum += vrow[u2];
        }
        sum += __shfl_xor_sync(0xffffffffu, sum, 1);
        sum += __shfl_xor_sync(0xffffffffu, sum, 2);
        float inv = 1.f / sum;
        #pragma unroll
        for (int nt = 0; nt < 8; nt++) {
            #pragma unroll
            for (int u = 0; u < 2; u++)
                sacc[nt][rh * 2 + u] = vrow[nt * 2 + u] * inv;
        }
    }

    // ---- Phase D: store P (tf32, paired) into sP[head] ----
    uint32_t* myP = sP + head * (64 * 72);
    {
        const int s0 = SL(2 * tid4), s1 = SL(2 * tid4 + 1);
        #pragma unroll
        for (int rh = 0; rh < 2; rh++) {
            int i = wrb + rh * 8 + gid;
            #pragma unroll
            for (int nt = 0; nt < 8; nt++) {
                myP[i * 72 + nt * 8 + s0] = f2tf(sacc[nt][rh * 2]);
                myP[i * 72 + nt * 8 + s1] = f2tf(sacc[nt][rh * 2 + 1]);
            }
        }
    }
    // named barrier: only the 4 warps of this head need sP[head] coherent
    asm volatile("bar.sync %0, %1;" :: "r"(1 + head), "r"(128) : "memory");

    // ---- Phase E: O = P @ V ----
    float oacc[4][4];
    #pragma unroll
    for (int b2 = 0; b2 < 4; b2++)
        #pragma unroll
        for (int c = 0; c < 4; c++) oacc[b2][c] = 0.f;
    const int dslot = SL(gid);

    #pragma unroll
    for (int kk = 0; kk < 8; kk++) {
        uint2 a0 = *(const uint2*)&myP[(wrb + gid) * 72 + kk * 8 + 2 * tid4];
        uint2 a1 = *(const uint2*)&myP[(wrb + 8 + gid) * 72 + kk * 8 + 2 * tid4];
        uint32_t a[4] = {a0.x, a1.x, a0.y, a1.y};
        #pragma unroll
        for (int nt = 0; nt < 4; nt++) {
            int dcol = hoff + nt * 8 + dslot;
            uint32_t b[2];
            b[0] = sV[(kk * 8 + tid4) * 136 + dcol];
            b[1] = sV[(kk * 8 + tid4 + 4) * 136 + dcol];
            mma8(oacc[nt], a, b);
        }
    }

    // ---- Phase F: store O (tf32, paired) into sO (overlays sA — dead) ----
    {
        const int s0 = SL(2 * tid4), s1 = SL(2 * tid4 + 1);
        #pragma unroll
        for (int nt = 0; nt < 4; nt++) {
            int grp = hoff + nt * 8;
            sO[(wrb + gid) * 136 + grp + s0]     = f2tf(oacc[nt][0]);
            sO[(wrb + gid) * 136 + grp + s1]     = f2tf(oacc[nt][1]);
            sO[(wrb + 8 + gid) * 136 + grp + s0] = f2tf(oacc[nt][2]);
            sO[(wrb + 8 + gid) * 136 + grp + s1] = f2tf(oacc[nt][3]);
        }
    }
    __syncthreads();                         // [FULL SYNC 3] sO visible

    // ---- Phase G: Y = O @ w_out + b_out (coalesced fragment LDGs) ----
    const int pwm = warp & 3, pwn = warp >> 2;   // 4x4 grid, tile 16x32
    float yacc[4][4];
    #pragma unroll
    for (int b2 = 0; b2 < 4; b2++)
        #pragma unroll
        for (int c = 0; c < 4; c++) yacc[b2][c] = 0.f;

    uint2 wA[4], wB[4];
    auto ldW = [&](uint2* dst, int kk) {
        #pragma unroll
        for (int nt = 0; nt < 4; nt++) {
            int n8g = pwn * 4 + nt;
            dst[nt] = *(const uint2*)&g_woutF[(n8g * 16 + kk) * 64 + lane * 2];
        }
    };
    ldW(wA, 0);
    ldW(wB, 1);

    auto doKk = [&](int kk, const uint2* wf) {
        uint2 a0 = *(const uint2*)&sO[(pwm * 16 + gid) * 136 + kk * 8 + 2 * tid4];
        uint2 a1 = *(const uint2*)&sO[(pwm * 16 + 8 + gid) * 136 + kk * 8 + 2 * tid4];
        uint32_t a[4] = {a0.x, a1.x, a0.y, a1.y};
        #pragma unroll
        for (int nt = 0; nt < 4; nt++)
            mma8(yacc[nt], a, (const uint32_t*)&wf[nt]);
    };
    #pragma unroll
    for (int kk = 0; kk < 16; kk += 2) {
        doKk(kk, wA);
        if (kk + 2 < 16) ldW(wA, kk + 2);
        doKk(kk + 1, wB);
        if (kk + 3 < 16) ldW(wB, kk + 3);
    }

    #pragma unroll
    for (int rh = 0; rh < 2; rh++) {
        int i = pwm * 16 + rh * 8 + gid;
        int ty = i >> 3, tx = i & 7;
        int h = (wy * 8 + ty + 4) & 127;
        int w = (wx * 8 + tx + 4) & 127;
        float* orow = out + (((size_t)bb * 128 + h) * 128 + w) * 128;
        #pragma unroll
        for (int nt = 0; nt < 4; nt++) {
            int c = pwn * 32 + nt * 8 + tid4 * 2;
            float2 v = make_float2(yacc[nt][rh * 2]     + sBO[c],
                                   yacc[nt][rh * 2 + 1] + sBO[c + 1]);
            *(float2*)(orow + c) = v;
        }
    }
}

// ===========================================================================
extern "C" void kernel_launch(void* const* d_in, const int* in_sizes, int n_in,
                              void* d_out, int out_size) {
    const float* x    = (const float*)d_in[0];
    const float* wqkv = (const float*)d_in[1];
    const float* wout = (const float*)d_in[2];
    const float* bout = (const float*)d_in[3];
    const float* pe   = (const float*)d_in[4];
    const float* ul   = (const float*)d_in[5];
    const float* lr   = (const float*)d_in[6];
    float* out = (float*)d_out;

    cudaFuncSetAttribute(fused_kernel, cudaFuncAttributeMaxDynamicSharedMemorySize, FU_SMEM);

    cvt_kernel<<<192, 256>>>(wqkv, wout);
    fused_kernel<<<4096, 512, FU_SMEM>>>(x, bout, pe, ul, lr, out);
}